// round 12
// baseline (speedup 1.0000x reference)
#include <cuda_runtime.h>
#include <cstdint>

// Decoder_90486370992920
// Inputs: d_in[0] partition [N,64] f32, d_in[1] abs_actions [64] f32,
//         d_in[2] u [N,64] f32, d_in[3] W [N,2,2] f32, d_in[4] b [N,2] f32
// Output: weights [N,2] f32 at [0,2N), actions [N,2] at [2N,4N)
//
// Key (R6, proven): m' = d*(1-p)*rcp(p), d = log2(u) < 0; rcp = raw approx +
// one Newton step; no cancellation -> stable single argmax flip (6.17e-4).
// argmax r/s == argmax m' -> FMAX reduce; exact-equality + ballot recovery.
//
// R12 delta vs R6: DENSE per-instruction access. R6 had lane sub load at
// sub*32B (+16B partner): each LDG.128 touched 8 half-consumed 128B lines
// (stride 32B, size 16B), 32 line-wavefronts per warp. Now lane sub loads
// at sub*16B and 128B+sub*16B: each LDG touches 4 fully-consumed lines ->
// 16 wavefronts, halving the l1tex queue term (cyc/LDG = Q + nL).
// Lane element map: A = {sub*4..sub*4+3} (line L0), B = {32+sub*4..+3} (L1).
// In-lane A-vs-B merge keeps A on ties (A indices < B indices always).
// weights = 1/(1+exp(-y)) accurate expf, subnormal flushed to 0 (XLA FTZ,
// established R2->R3). actions = (w>0).

static constexpr int M = 64;
static constexpr int LPA = 8;            // lanes per agent
static constexpr int THREADS = 256;
static constexpr int AGENTS_PER_BLOCK = THREADS / LPA;   // 32

__device__ __forceinline__ float key_m(float p, float uu)
{
    float q = 1.0f - p;                                 // exact for p>=0.5, <=1/2 ulp else
    float t;
    asm("rcp.approx.f32 %0, %1;" : "=f"(t) : "f"(p));   // ~1/p, raw approx
    t = t * __fmaf_rn(-p, t, 2.0f);                     // Newton -> ~0.5 ulp
    float d = __log2f(uu);                              // MUFU.LG2, d < 0
    return (d * q) * t;                                 // m' = d*(1-p)/p < 0
}

__global__ __launch_bounds__(THREADS)
void decoder_kernel(const float* __restrict__ part,
                    const float* __restrict__ absa,
                    const float* __restrict__ u,
                    const float* __restrict__ W,
                    const float* __restrict__ b,
                    float* __restrict__ out,
                    int nAgents,
                    long long outSize)
{
    __shared__ float sabs[M];
    if (threadIdx.x < M) sabs[threadIdx.x] = absa[threadIdx.x];
    __syncthreads();

    const int lane = threadIdx.x & 31;
    const int sub  = lane & (LPA - 1);          // 0..7 within agent
    const int grp  = lane >> 3;                 // agent slot within warp (0..3)
    const int gwarp = (int)((blockIdx.x * (unsigned)blockDim.x + threadIdx.x) >> 5);
    const int agent = gwarp * 4 + grp;

    const int ag = agent < nAgents ? agent : (nAgents - 1);
    const size_t row = (size_t)ag * M;

    // DENSE loads: pA/uA cover line L0 (first 32 floats), pB/uB line L1.
    // Per LDG instruction: 8 lanes x 16B contiguous per agent = 4 full lines.
    const float4 pA = __ldg(reinterpret_cast<const float4*>(part + row + sub * 4));
    const float4 pB = __ldg(reinterpret_cast<const float4*>(part + row + 32 + sub * 4));
    const float4 uA = __ldg(reinterpret_cast<const float4*>(u + row + sub * 4));
    const float4 uB = __ldg(reinterpret_cast<const float4*>(u + row + 32 + sub * 4));

    float a0 = key_m(pA.x, uA.x);
    float a1 = key_m(pA.y, uA.y);
    float a2 = key_m(pA.z, uA.z);
    float a3 = key_m(pA.w, uA.w);
    float b0 = key_m(pB.x, uB.x);
    float b1 = key_m(pB.y, uB.y);
    float b2 = key_m(pB.z, uB.z);
    float b3 = key_m(pB.w, uB.w);

    // within-lane max
    float kmA = fmaxf(fmaxf(a0, a1), fmaxf(a2, a3));
    float kmB = fmaxf(fmaxf(b0, b1), fmaxf(b2, b3));
    float km  = fmaxf(kmA, kmB);

    // in-lane index recovery (lowest slot wins within each group; A wins ties)
    const int baseA = sub * 4;
    int li = 1 << 20;
    if (b3 == km) li = baseA + 32 + 3;
    if (b2 == km) li = baseA + 32 + 2;
    if (b1 == km) li = baseA + 32 + 1;
    if (b0 == km) li = baseA + 32 + 0;
    if (a3 == km) li = baseA + 3;
    if (a2 == km) li = baseA + 2;
    if (a1 == km) li = baseA + 1;
    if (a0 == km) li = baseA + 0;

    float klane = km;

    // cross-lane max over the 8 lanes of this agent
    #pragma unroll
    for (int off = 4; off > 0; off >>= 1)
        km = fmaxf(km, __shfl_xor_sync(0xffffffffu, km, off, LPA));

    unsigned bal = __ballot_sync(0xffffffffu, klane == km);
    unsigned gmask = (bal >> (grp * LPA)) & 0xffu;    // hits within this agent's lanes
    int leader = __ffs((int)gmask) - 1;               // lowest hitting lane
    int widx = __shfl_sync(0xffffffffu, li, grp * LPA + leader);

    if (sub == 0 && agent < nAgents) {
        const float x0 = (float)widx;
        const float x1 = sabs[widx];

        const float4 w  = __ldg(reinterpret_cast<const float4*>(W + (size_t)agent * 4));
        const float2 bb = __ldg(reinterpret_cast<const float2*>(b + (size_t)agent * 2));

        float y0 = fmaf(w.x, x0, fmaf(w.y, x1, bb.x));
        float y1 = fmaf(w.z, x0, fmaf(w.w, x1, bb.y));

        // naive sigmoid, accurate expf, FTZ flush of subnormal results
        float s0 = 1.0f / (1.0f + expf(-y0));
        float s1 = 1.0f / (1.0f + expf(-y1));
        if (s0 < 1.17549435e-38f) s0 = 0.0f;
        if (s1 < 1.17549435e-38f) s1 = 0.0f;

        reinterpret_cast<float2*>(out + (size_t)agent * 2)[0] = make_float2(s0, s1);

        if (outSize >= 4LL * nAgents) {
            float c0 = (s0 > 0.0f) ? 1.0f : 0.0f;
            float c1 = (s1 > 0.0f) ? 1.0f : 0.0f;
            reinterpret_cast<float2*>(out + 2LL * nAgents + (size_t)agent * 2)[0] =
                make_float2(c0, c1);
        }
    }
}

extern "C" void kernel_launch(void* const* d_in, const int* in_sizes, int n_in,
                              void* d_out, int out_size)
{
    const float* part = (const float*)d_in[0];
    const float* absa = (const float*)d_in[1];
    const float* u    = (const float*)d_in[2];
    const float* W    = (const float*)d_in[3];
    const float* b    = (const float*)d_in[4];
    float* out = (float*)d_out;

    const int nAgents = in_sizes[0] / M;
    const int blocks = (nAgents + AGENTS_PER_BLOCK - 1) / AGENTS_PER_BLOCK;

    decoder_kernel<<<blocks, THREADS>>>(part, absa, u, W, b, out, nAgents,
                                        (long long)out_size);
}

// round 13
// speedup vs baseline: 1.0237x; 1.0237x over previous
#include <cuda_runtime.h>
#include <cstdint>

// Decoder_90486370992920
// Inputs: d_in[0] partition [N,64] f32, d_in[1] abs_actions [64] f32,
//         d_in[2] u [N,64] f32, d_in[3] W [N,2,2] f32, d_in[4] b [N,2] f32
// Output: weights [N,2] f32 at [0,2N), actions [N,2] at [2N,4N)
//
// Key (proven R6): m' = d*(1-p)*rcp(p), d = log2(u) < 0; rcp = raw approx +
// one Newton step; no cancellation -> stable single argmax flip (6.17e-4).
// argmax r/s == argmax m' -> FMAX reduce; exact-equality + ballot recovery.
//
// R13 = R12 dense-line layout (each LDG.128 touches 4 fully-consumed 128B
// lines; L1 wavefronts halved, verified 45%->29.5% in ncu) + 512-thread
// blocks (halves CTA count; per-warp SASS identical).
// Plateau evidence: R6/R11/R12 all 92.5us kernel @ ~5970 GB/s across wildly
// different occupancy/hints/L1 -> hard achievable-BW ceiling; bytes (552MB)
// are algorithmically irreducible for a full argmax.
// weights = 1/(1+exp(-y)) accurate expf, subnormal flushed to 0 (XLA FTZ,
// established R2->R3). actions = (w>0).

static constexpr int M = 64;
static constexpr int LPA = 8;            // lanes per agent
static constexpr int THREADS = 512;
static constexpr int AGENTS_PER_BLOCK = THREADS / LPA;   // 64

__device__ __forceinline__ float key_m(float p, float uu)
{
    float q = 1.0f - p;                                 // exact for p>=0.5, <=1/2 ulp else
    float t;
    asm("rcp.approx.f32 %0, %1;" : "=f"(t) : "f"(p));   // ~1/p, raw approx
    t = t * __fmaf_rn(-p, t, 2.0f);                     // Newton -> ~0.5 ulp
    float d = __log2f(uu);                              // MUFU.LG2, d < 0
    return (d * q) * t;                                 // m' = d*(1-p)/p < 0
}

__global__ __launch_bounds__(THREADS)
void decoder_kernel(const float* __restrict__ part,
                    const float* __restrict__ absa,
                    const float* __restrict__ u,
                    const float* __restrict__ W,
                    const float* __restrict__ b,
                    float* __restrict__ out,
                    int nAgents,
                    long long outSize)
{
    __shared__ float sabs[M];
    if (threadIdx.x < M) sabs[threadIdx.x] = absa[threadIdx.x];
    __syncthreads();

    const int lane = threadIdx.x & 31;
    const int sub  = lane & (LPA - 1);          // 0..7 within agent
    const int grp  = lane >> 3;                 // agent slot within warp (0..3)
    const int gwarp = (int)((blockIdx.x * (unsigned)blockDim.x + threadIdx.x) >> 5);
    const int agent = gwarp * 4 + grp;

    const int ag = agent < nAgents ? agent : (nAgents - 1);
    const size_t row = (size_t)ag * M;

    // DENSE loads: A covers line L0 (floats 0..31), B line L1 (32..63).
    // Per LDG instruction: 8 lanes x 16B contiguous per agent = 4 full lines.
    const float4 pA = __ldg(reinterpret_cast<const float4*>(part + row + sub * 4));
    const float4 pB = __ldg(reinterpret_cast<const float4*>(part + row + 32 + sub * 4));
    const float4 uA = __ldg(reinterpret_cast<const float4*>(u + row + sub * 4));
    const float4 uB = __ldg(reinterpret_cast<const float4*>(u + row + 32 + sub * 4));

    float a0 = key_m(pA.x, uA.x);
    float a1 = key_m(pA.y, uA.y);
    float a2 = key_m(pA.z, uA.z);
    float a3 = key_m(pA.w, uA.w);
    float b0 = key_m(pB.x, uB.x);
    float b1 = key_m(pB.y, uB.y);
    float b2 = key_m(pB.z, uB.z);
    float b3 = key_m(pB.w, uB.w);

    // within-lane max
    float kmA = fmaxf(fmaxf(a0, a1), fmaxf(a2, a3));
    float kmB = fmaxf(fmaxf(b0, b1), fmaxf(b2, b3));
    float km  = fmaxf(kmA, kmB);

    // in-lane index recovery (lowest slot wins; A group (lower idx) wins ties)
    const int baseA = sub * 4;
    int li = 1 << 20;
    if (b3 == km) li = baseA + 32 + 3;
    if (b2 == km) li = baseA + 32 + 2;
    if (b1 == km) li = baseA + 32 + 1;
    if (b0 == km) li = baseA + 32 + 0;
    if (a3 == km) li = baseA + 3;
    if (a2 == km) li = baseA + 2;
    if (a1 == km) li = baseA + 1;
    if (a0 == km) li = baseA + 0;

    float klane = km;

    // cross-lane max over the 8 lanes of this agent
    #pragma unroll
    for (int off = 4; off > 0; off >>= 1)
        km = fmaxf(km, __shfl_xor_sync(0xffffffffu, km, off, LPA));

    unsigned bal = __ballot_sync(0xffffffffu, klane == km);
    unsigned gmask = (bal >> (grp * LPA)) & 0xffu;    // hits within this agent's lanes
    int leader = __ffs((int)gmask) - 1;               // lowest hitting lane
    int widx = __shfl_sync(0xffffffffu, li, grp * LPA + leader);

    if (sub == 0 && agent < nAgents) {
        const float x0 = (float)widx;
        const float x1 = sabs[widx];

        const float4 w  = __ldg(reinterpret_cast<const float4*>(W + (size_t)agent * 4));
        const float2 bb = __ldg(reinterpret_cast<const float2*>(b + (size_t)agent * 2));

        float y0 = fmaf(w.x, x0, fmaf(w.y, x1, bb.x));
        float y1 = fmaf(w.z, x0, fmaf(w.w, x1, bb.y));

        // naive sigmoid, accurate expf, FTZ flush of subnormal results
        float s0 = 1.0f / (1.0f + expf(-y0));
        float s1 = 1.0f / (1.0f + expf(-y1));
        if (s0 < 1.17549435e-38f) s0 = 0.0f;
        if (s1 < 1.17549435e-38f) s1 = 0.0f;

        reinterpret_cast<float2*>(out + (size_t)agent * 2)[0] = make_float2(s0, s1);

        if (outSize >= 4LL * nAgents) {
            float c0 = (s0 > 0.0f) ? 1.0f : 0.0f;
            float c1 = (s1 > 0.0f) ? 1.0f : 0.0f;
            reinterpret_cast<float2*>(out + 2LL * nAgents + (size_t)agent * 2)[0] =
                make_float2(c0, c1);
        }
    }
}

extern "C" void kernel_launch(void* const* d_in, const int* in_sizes, int n_in,
                              void* d_out, int out_size)
{
    const float* part = (const float*)d_in[0];
    const float* absa = (const float*)d_in[1];
    const float* u    = (const float*)d_in[2];
    const float* W    = (const float*)d_in[3];
    const float* b    = (const float*)d_in[4];
    float* out = (float*)d_out;

    const int nAgents = in_sizes[0] / M;
    const int blocks = (nAgents + AGENTS_PER_BLOCK - 1) / AGENTS_PER_BLOCK;

    decoder_kernel<<<blocks, THREADS>>>(part, absa, u, W, b, out, nAgents,
                                        (long long)out_size);
}

// round 14
// speedup vs baseline: 1.0435x; 1.0193x over previous
#include <cuda_runtime.h>
#include <cstdint>

// Decoder_90486370992920 — FINAL (R6, best of 8 measured variants)
// Inputs: d_in[0] partition [N,64] f32, d_in[1] abs_actions [64] f32,
//         d_in[2] u [N,64] f32, d_in[3] W [N,2,2] f32, d_in[4] b [N,2] f32
// Output: weights [N,2] f32 at [0,2N), actions [N,2] at [2N,4N)
//
// Math: argmax_m (logit(p)+gumbel) == argmax_m r/s, r=p/(1-p), s=-ln u.
// Cancellation-free reciprocal key: m' = d*(1-p)*rcp(p), d=log2(u)<0,
// rcp = raw approx + 1 Newton (0.5 ulp); argmax r/s == argmax m' -> plain
// FMAX reduce. Noise class: LG2-dominated -> stable single argmax flip in
// 1M agents (rel_err 6.17e-4, bit-identical across R3/R4/R6/R11-R13).
// Index recovery: FMAX propagates exact bits -> equality match + ballot;
// lowest lane/slot first == reference first-occurrence tie rule.
// weights = 1/(1+exp(-y)) with accurate expf; subnormal results flushed to
// exactly 0 (XLA FTZ semantics — established via the R1/R2 mismatch-count
// forensics: 546 -> exp-overflow cutoff, residual 75 -> subnormal band).
// actions = (w > 0).
//
// Perf: 92.5us kernel @ 5970 GB/s on 552MB irreducible traffic — measured
// plateau (~87% of achievable LTS/HBM ceiling). Perturbations measured and
// rejected: .cs/.cg hints (+0.3/+4us), 16-elem lanes (+1.6), persistent
// grid (+22), W/b hoist (0), dense-line remap (0, L1 45->30% but DRAM-bound),
// 512-thread blocks (+1.6).

static constexpr int M = 64;
static constexpr int LPA = 8;            // lanes per agent
static constexpr int EPL = 8;            // elements per lane
static constexpr int THREADS = 256;
static constexpr int AGENTS_PER_BLOCK = THREADS / LPA;   // 32

__device__ __forceinline__ float key_m(float p, float uu)
{
    float q = 1.0f - p;                                 // exact for p>=0.5, <=1/2 ulp else
    float t;
    asm("rcp.approx.f32 %0, %1;" : "=f"(t) : "f"(p));   // ~1/p, raw approx
    t = t * __fmaf_rn(-p, t, 2.0f);                     // Newton -> ~0.5 ulp
    float d = __log2f(uu);                              // MUFU.LG2, d < 0
    return (d * q) * t;                                 // m' = d*(1-p)/p < 0
}

__global__ __launch_bounds__(THREADS)
void decoder_kernel(const float* __restrict__ part,
                    const float* __restrict__ absa,
                    const float* __restrict__ u,
                    const float* __restrict__ W,
                    const float* __restrict__ b,
                    float* __restrict__ out,
                    int nAgents,
                    long long outSize)
{
    __shared__ float sabs[M];
    if (threadIdx.x < M) sabs[threadIdx.x] = absa[threadIdx.x];
    __syncthreads();

    const int lane = threadIdx.x & 31;
    const int sub  = lane & (LPA - 1);          // 0..7 within agent
    const int grp  = lane >> 3;                 // agent slot within warp (0..3)
    const int gwarp = (int)((blockIdx.x * (unsigned)blockDim.x + threadIdx.x) >> 5);
    const int agent = gwarp * 4 + grp;

    const int ag = agent < nAgents ? agent : (nAgents - 1);
    const size_t rowBase = (size_t)ag * M + sub * EPL;

    const float4 p0 = __ldg(reinterpret_cast<const float4*>(part + rowBase));
    const float4 p1 = __ldg(reinterpret_cast<const float4*>(part + rowBase + 4));
    const float4 u0 = __ldg(reinterpret_cast<const float4*>(u + rowBase));
    const float4 u1 = __ldg(reinterpret_cast<const float4*>(u + rowBase + 4));

    float m0 = key_m(p0.x, u0.x);
    float m1 = key_m(p0.y, u0.y);
    float m2 = key_m(p0.z, u0.z);
    float m3 = key_m(p0.w, u0.w);
    float m4 = key_m(p1.x, u1.x);
    float m5 = key_m(p1.y, u1.y);
    float m6 = key_m(p1.z, u1.z);
    float m7 = key_m(p1.w, u1.w);

    // within-lane max (== argmax of r/s)
    float a = fmaxf(fmaxf(m0, m1), fmaxf(m2, m3));
    float c = fmaxf(fmaxf(m4, m5), fmaxf(m6, m7));
    float km = fmaxf(a, c);

    // cross-lane max over the 8 lanes of this agent
    #pragma unroll
    for (int off = 4; off > 0; off >>= 1)
        km = fmaxf(km, __shfl_xor_sync(0xffffffffu, km, off, LPA));

    // index recovery: exact equality against km; lowest slot wins within lane
    const int base = sub * EPL;
    int li = 1 << 20;
    if (m7 == km) li = base + 7;
    if (m6 == km) li = base + 6;
    if (m5 == km) li = base + 5;
    if (m4 == km) li = base + 4;
    if (m3 == km) li = base + 3;
    if (m2 == km) li = base + 2;
    if (m1 == km) li = base + 1;
    if (m0 == km) li = base + 0;

    unsigned bal = __ballot_sync(0xffffffffu, li < (1 << 20));
    unsigned gmask = (bal >> (grp * LPA)) & 0xffu;    // hits within this agent's lanes
    int leader = __ffs((int)gmask) - 1;               // lowest lane -> lowest index
    int widx = __shfl_sync(0xffffffffu, li, grp * LPA + leader);

    if (sub == 0 && agent < nAgents) {
        const float x0 = (float)widx;
        const float x1 = sabs[widx];

        const float4 w  = __ldg(reinterpret_cast<const float4*>(W + (size_t)agent * 4));
        const float2 bb = __ldg(reinterpret_cast<const float2*>(b + (size_t)agent * 2));

        float y0 = fmaf(w.x, x0, fmaf(w.y, x1, bb.x));
        float y1 = fmaf(w.z, x0, fmaf(w.w, x1, bb.y));

        // naive sigmoid, accurate expf, FTZ flush of subnormal results
        float s0 = 1.0f / (1.0f + expf(-y0));
        float s1 = 1.0f / (1.0f + expf(-y1));
        if (s0 < 1.17549435e-38f) s0 = 0.0f;
        if (s1 < 1.17549435e-38f) s1 = 0.0f;

        reinterpret_cast<float2*>(out + (size_t)agent * 2)[0] = make_float2(s0, s1);

        if (outSize >= 4LL * nAgents) {
            float a0 = (s0 > 0.0f) ? 1.0f : 0.0f;
            float a1 = (s1 > 0.0f) ? 1.0f : 0.0f;
            reinterpret_cast<float2*>(out + 2LL * nAgents + (size_t)agent * 2)[0] =
                make_float2(a0, a1);
        }
    }
}

extern "C" void kernel_launch(void* const* d_in, const int* in_sizes, int n_in,
                              void* d_out, int out_size)
{
    const float* part = (const float*)d_in[0];
    const float* absa = (const float*)d_in[1];
    const float* u    = (const float*)d_in[2];
    const float* W    = (const float*)d_in[3];
    const float* b    = (const float*)d_in[4];
    float* out = (float*)d_out;

    const int nAgents = in_sizes[0] / M;
    const int blocks = (nAgents + AGENTS_PER_BLOCK - 1) / AGENTS_PER_BLOCK;

    decoder_kernel<<<blocks, THREADS>>>(part, absa, u, W, b, out, nAgents,
                                        (long long)out_size);
}